// round 14
// baseline (speedup 1.0000x reference)
#include <cuda_runtime.h>
#include <math.h>

#define H 1024
#define S 2048
#define VOCAB 50257

// ---------------- scratch (__device__ globals) -----------------------------
__device__ float g_h0[H];
__device__ float g_h1[H];
__device__ float g_energ[S];
__device__ float g_am[256];          // attention (max, expsum) partials
__device__ float g_as[256];
__device__ float g_ctx_part[256 * H];
__device__ float g_ctx[H];
__device__ float g_xout[2 * H];      // [h1, ctx]
__device__ float g_lm[64];           // logit lse partials
__device__ float g_ls[64];
__device__ unsigned g_ctr;           // completion counter for k_energy_ctx
__device__ unsigned g_done;          // release flag

__device__ __forceinline__ float wred(float v) {
#pragma unroll
    for (int o = 16; o; o >>= 1) v += __shfl_xor_sync(0xffffffffu, v, o);
    return v;
}
__device__ __forceinline__ float sig_(float x) { return 1.0f / (1.0f + expf(-x)); }

// online (max, expsum) merge — deterministic, guards empty partials
__device__ __forceinline__ void msmerge(float& m1, float& s1, float m2, float s2) {
    if (s2 == 0.0f) return;
    if (s1 == 0.0f) { m1 = m2; s1 = s2; return; }
    if (m2 > m1) { float tm = m1; m1 = m2; m2 = tm; float ts = s1; s1 = s2; s2 = ts; }
    s1 += s2 * expf(m2 - m1);
}

// ---------------- fused GRU layer: one BLOCK (256 thr) per output j --------
template <int N, bool GATHER>
__global__ void k_gru(const float* __restrict__ Wih, const float* __restrict__ Whh,
                      const float* __restrict__ bih, const float* __restrict__ bhh,
                      const float* __restrict__ xin,
                      const float* __restrict__ emb, const int* __restrict__ word,
                      const float* __restrict__ lastctx,
                      const float* __restrict__ hprev,
                      float* __restrict__ hout, float* __restrict__ hcopy,
                      float* __restrict__ xcopy) {
    __shared__ float smem[6][8];
    int j = blockIdx.x;
    int tid = threadIdx.x;
    int lane = tid & 31, warp = tid >> 5;

    // reset the energy_ctx completion counters once per run (runs before it)
    if (GATHER && j == 0 && tid == 0) { g_ctr = 0; g_done = 0; }

    const float4* wr4 = reinterpret_cast<const float4*>(Wih + (size_t)j * N);
    const float4* wz4 = reinterpret_cast<const float4*>(Wih + (size_t)(H + j) * N);
    const float4* wn4 = reinterpret_cast<const float4*>(Wih + (size_t)(2 * H + j) * N);
    const float4* ur4 = reinterpret_cast<const float4*>(Whh + (size_t)j * H);
    const float4* uz4 = reinterpret_cast<const float4*>(Whh + (size_t)(H + j) * H);
    const float4* un4 = reinterpret_cast<const float4*>(Whh + (size_t)(2 * H + j) * H);
    const float4* h4  = reinterpret_cast<const float4*>(hprev);

    float ir = 0.f, iz = 0.f, in_ = 0.f, hr = 0.f, hz = 0.f, hn = 0.f;

    if (GATHER) {
        const float4* e4 = reinterpret_cast<const float4*>(emb) + (size_t)word[0] * (H / 4);
        const float4* c4 = reinterpret_cast<const float4*>(lastctx);
#pragma unroll
        for (int i = tid; i < N / 4; i += 256) {
            float4 xv = (i < H / 4) ? e4[i] : c4[i - H / 4];
            float4 a = wr4[i], b = wz4[i], c = wn4[i];
            ir  += a.x * xv.x + a.y * xv.y + a.z * xv.z + a.w * xv.w;
            iz  += b.x * xv.x + b.y * xv.y + b.z * xv.z + b.w * xv.w;
            in_ += c.x * xv.x + c.y * xv.y + c.z * xv.z + c.w * xv.w;
        }
    } else {
        const float4* x4 = reinterpret_cast<const float4*>(xin);
#pragma unroll
        for (int i = tid; i < N / 4; i += 256) {
            float4 xv = x4[i];
            float4 a = wr4[i], b = wz4[i], c = wn4[i];
            ir  += a.x * xv.x + a.y * xv.y + a.z * xv.z + a.w * xv.w;
            iz  += b.x * xv.x + b.y * xv.y + b.z * xv.z + b.w * xv.w;
            in_ += c.x * xv.x + c.y * xv.y + c.z * xv.z + c.w * xv.w;
        }
    }
    {   // H/4 = 256 float4 -> exactly one iteration per thread
        float4 hv = h4[tid];
        float4 a = ur4[tid], b = uz4[tid], c = un4[tid];
        hr = a.x * hv.x + a.y * hv.y + a.z * hv.z + a.w * hv.w;
        hz = b.x * hv.x + b.y * hv.y + b.z * hv.z + b.w * hv.w;
        hn = c.x * hv.x + c.y * hv.y + c.z * hv.z + c.w * hv.w;
    }
    ir = wred(ir); iz = wred(iz); in_ = wred(in_);
    hr = wred(hr); hz = wred(hz); hn = wred(hn);
    if (lane == 0) {
        smem[0][warp] = ir; smem[1][warp] = iz; smem[2][warp] = in_;
        smem[3][warp] = hr; smem[4][warp] = hz; smem[5][warp] = hn;
    }
    __syncthreads();
    if (tid == 0) {
        float v[6];
#pragma unroll
        for (int g = 0; g < 6; ++g) {
            float s = smem[g][0];
#pragma unroll
            for (int w = 1; w < 8; ++w) s += smem[g][w];
            v[g] = s;
        }
        float r  = sig_((v[0] + bih[j]) + (v[3] + bhh[j]));
        float z  = sig_((v[1] + bih[H + j]) + (v[4] + bhh[H + j]));
        float nn = tanhf((v[2] + bih[2 * H + j]) + r * (v[5] + bhh[2 * H + j]));
        float h  = (1.0f - z) * nn + z * hprev[j];
        hout[j] = h;
        hcopy[j] = h;
        if (xcopy) xcopy[j] = h;
    }
}

// ---------------- energies + partial context + fused final reduce ----------
// 256 blocks x 256 threads; warp per s-row (8 rows/block).
// Phase 1 (all blocks): energies, block-local softmax partial, unnormalized
//   partial context written to g_ctx_part.
// Phase 2 (last 32 blocks to finish, after release flag): each handles 1/32
//   of the d-space: global (M,Z) tree, attention weights, final ctx.
__global__ void k_energy_ctx(const float* __restrict__ enc, const float* __restrict__ h1,
                             float* __restrict__ ctx_out, float* __restrict__ attn_out) {
    __shared__ float se[8];
    __shared__ float sbuf[1024];            // phase1: sctx; phase2: sm/ss/ssc/spart
    __shared__ unsigned srank;
    int tid = threadIdx.x;
    int lane = tid & 31, warp = tid >> 5;
    int s = blockIdx.x * 8 + warp;

    const float4* w4 = reinterpret_cast<const float4*>(enc) + (size_t)s * 256;
    const float4* x4 = reinterpret_cast<const float4*>(h1);

    float4 row[8];                          // this lane's slice of the enc row
    float e = 0.f;
#pragma unroll
    for (int k = 0; k < 8; ++k) {
        float4 a = w4[lane + 32 * k];
        float4 c = x4[lane + 32 * k];
        row[k] = a;
        e += a.x * c.x + a.y * c.y + a.z * c.z + a.w * c.w;
    }
    e = wred(e);
    e = __shfl_sync(0xffffffffu, e, 0);
    if (lane == 0) { g_energ[s] = e; se[warp] = e; }

    float4* sctx4 = reinterpret_cast<float4*>(sbuf);
    sctx4[tid] = make_float4(0.f, 0.f, 0.f, 0.f);
    __syncthreads();

    float m = se[0];
#pragma unroll
    for (int w = 1; w < 8; ++w) m = fmaxf(m, se[w]);
    float wgt = expf(e - m);

    // deterministic warp-ordered accumulation into smem
#pragma unroll
    for (int w = 0; w < 8; ++w) {
        if (warp == w) {
#pragma unroll
            for (int k = 0; k < 8; ++k) {
                int i = lane + 32 * k;
                float4 acc = sctx4[i];
                acc.x += wgt * row[k].x; acc.y += wgt * row[k].y;
                acc.z += wgt * row[k].z; acc.w += wgt * row[k].w;
                sctx4[i] = acc;
            }
        }
        __syncthreads();
    }

    reinterpret_cast<float4*>(g_ctx_part + (size_t)blockIdx.x * H)[tid] = sctx4[tid];
    if (tid == 0) {
        float sum = 0.f;
#pragma unroll
        for (int w = 0; w < 8; ++w) sum += expf(se[w] - m);
        g_am[blockIdx.x] = m;
        g_as[blockIdx.x] = sum;
    }

    // ---- completion protocol ----
    __threadfence();                        // partials visible before count
    __syncthreads();                        // all threads' writes fenced
    if (tid == 0) srank = atomicAdd(&g_ctr, 1);
    __syncthreads();
    unsigned rank = srank;
    if (rank == 255) {                      // all 256 partials are visible
        __threadfence();
        if (tid == 0) atomicExch(&g_done, 1);
    }
    if (rank < 224) return;                 // not one of the last 32

    // ---- phase 2: last 32 blocks each reduce one 32-d slice ----
    if (tid == 0) {
        while (atomicAdd(&g_done, 0) == 0) __nanosleep(64);
    }
    __syncthreads();
    __threadfence();
    int slice = (int)rank - 224;            // 0..31
    int dbase = slice * 32;

    float* sm  = sbuf;                      // reuse: [0,256)
    float* ss  = sbuf + 256;                // [256,512)
    float* ssc = sbuf + 512;                // [512,768)
    float* spart = sbuf + 768;              // [768,1024) -> [8][32]
    __syncthreads();                        // done with sctx4 contents
    sm[tid] = g_am[tid]; ss[tid] = g_as[tid];
    __syncthreads();
    float myM = sm[tid];
#pragma unroll
    for (int off = 128; off >= 1; off >>= 1) {
        if (tid < off) msmerge(sm[tid], ss[tid], sm[tid + off], ss[tid + off]);
        __syncthreads();
    }
    float M = sm[0], Z = ss[0];
    __syncthreads();
    ssc[tid] = expf(myM - M);
    __syncthreads();
    float invZ = 1.0f / Z;

    if (tid < 64) {
        int sidx = slice * 64 + tid;
        attn_out[sidx] = expf(g_energ[sidx] - M) * invZ;
    }

    // warp w sums b in [32w, 32w+32) for d = dbase + lane (coalesced)
    float acc = 0.f;
#pragma unroll
    for (int i = 0; i < 32; ++i) {
        int b = warp * 32 + i;
        acc += ssc[b] * g_ctx_part[(size_t)b * H + dbase + lane];
    }
    spart[warp * 32 + lane] = acc;
    __syncthreads();
    if (warp == 0) {
        float sum = spart[lane];
#pragma unroll
        for (int w = 1; w < 8; ++w) sum += spart[w * 32 + lane];
        float c = sum * invZ;
        int d = dbase + lane;
        g_ctx[d] = c;
        ctx_out[d] = c;
        g_xout[H + d] = c;
    }
}

// vocab GEMV: warp per row, full 2048 cols, bias fused (R5 plain version)
__global__ void k_vocab(const float* __restrict__ W, const float* __restrict__ b,
                        float* __restrict__ logits) {
    int v = (blockIdx.x * blockDim.x + threadIdx.x) >> 5;
    int lane = threadIdx.x & 31;
    if (v >= VOCAB) return;
    const float4* w4 = reinterpret_cast<const float4*>(W) + (size_t)v * 512;
    const float4* x4 = reinterpret_cast<const float4*>(g_xout);
    float s = 0.f;
#pragma unroll 8
    for (int i = lane; i < 512; i += 32) {
        float4 a = w4[i], c = x4[i];
        s += a.x * c.x + a.y * c.y + a.z * c.z + a.w * c.w;
    }
    s = wred(s);
    if (lane == 0) logits[v] = s + b[v];
}

// logit lse stage 1: 64 blocks x 256 threads, online (m,s) per block
__global__ void k_lse1(const float* __restrict__ logits) {
    __shared__ float sm[8], ss[8];
    const int CH = 786;
    int b = blockIdx.x;
    int lo = b * CH;
    int hi = min(lo + CH, VOCAB);
    int lane = threadIdx.x & 31, warp = threadIdx.x >> 5;
    float m = -INFINITY, s = 0.f;
    for (int v = lo + threadIdx.x; v < hi; v += 256) {
        float x = logits[v];
        if (x > m) { s = s * expf(m - x) + 1.0f; m = x; }
        else s += expf(x - m);
    }
#pragma unroll
    for (int o = 16; o; o >>= 1) {
        float m2 = __shfl_xor_sync(0xffffffffu, m, o);
        float s2 = __shfl_xor_sync(0xffffffffu, s, o);
        msmerge(m, s, m2, s2);
    }
    if (lane == 0) { sm[warp] = m; ss[warp] = s; }
    __syncthreads();
    if (threadIdx.x == 0) {
        float M = sm[0], Ssum = ss[0];
#pragma unroll
        for (int w = 1; w < 8; ++w) msmerge(M, Ssum, sm[w], ss[w]);
        g_lm[b] = M; g_ls[b] = Ssum;
    }
}

// finalize: each block recomputes the final LSE from 64 partials (L2-hot),
// then subtracts. Deterministic identical tree in every block.
__global__ void k_finalize(float* __restrict__ logits) {
    __shared__ float sm[64], ss[64];
    int t = threadIdx.x;
    if (t < 64) { sm[t] = g_lm[t]; ss[t] = g_ls[t]; }
    __syncthreads();
#pragma unroll
    for (int off = 32; off >= 1; off >>= 1) {
        if (t < off) msmerge(sm[t], ss[t], sm[t + off], ss[t + off]);
        __syncthreads();
    }
    float lse = sm[0] + logf(ss[0]);
    int v = blockIdx.x * blockDim.x + t;
    if (v < VOCAB) logits[v] -= lse;
}

// ---------------- launch ---------------------------------------------------

extern "C" void kernel_launch(void* const* d_in, const int* in_sizes, int n_in,
                              void* d_out, int out_size) {
    const int*   word     = (const int*)  d_in[0];
    const float* last_ctx = (const float*)d_in[1];
    const float* last_hid = (const float*)d_in[2];   // (2,1,H)
    const float* enc      = (const float*)d_in[3];   // (S,1,H)
    const float* emb      = (const float*)d_in[4];
    const float* W_ih0    = (const float*)d_in[5];
    const float* W_hh0    = (const float*)d_in[6];
    const float* b_ih0    = (const float*)d_in[7];
    const float* b_hh0    = (const float*)d_in[8];
    const float* W_ih1    = (const float*)d_in[9];
    const float* W_hh1    = (const float*)d_in[10];
    const float* b_ih1    = (const float*)d_in[11];
    const float* b_hh1    = (const float*)d_in[12];
    const float* W_out    = (const float*)d_in[13];
    const float* b_out    = (const float*)d_in[14];

    float* out       = (float*)d_out;
    float* out_logit = out;                  // [0, V)
    float* out_ctx   = out + VOCAB;          // context
    float* out_h0    = out + VOCAB + H;      // hidden[0]
    float* out_h1    = out + VOCAB + 2 * H;  // hidden[1]
    float* out_attn  = out + VOCAB + 3 * H;  // attn weights

    float *ph0, *ph1, *pxout;
    cudaGetSymbolAddress((void**)&ph0, g_h0);
    cudaGetSymbolAddress((void**)&ph1, g_h1);
    cudaGetSymbolAddress((void**)&pxout, g_xout);

    // 1-2) fused GRU layers; layer 1 also writes g_xout[0..H) = h1
    k_gru<2048, true><<<H, 256>>>(W_ih0, W_hh0, b_ih0, b_hh0, nullptr,
                                  emb, word, last_ctx, last_hid, ph0, out_h0,
                                  (float*)nullptr);
    k_gru<1024, false><<<H, 256>>>(W_ih1, W_hh1, b_ih1, b_hh1, ph0,
                                   nullptr, nullptr, nullptr, last_hid + H, ph1, out_h1,
                                   pxout);

    // 3) attention: single kernel (energies + partials + fused final reduce)
    k_energy_ctx<<<256, 256>>>(enc, ph1, out_ctx, out_attn);

    // 4) vocab logits (bias fused)
    k_vocab<<<(VOCAB * 32 + 255) / 256, 256>>>(W_out, b_out, out_logit);

    // 5-6) log_softmax
    k_lse1<<<64, 256>>>(out_logit);
    k_finalize<<<(VOCAB + 255) / 256, 256>>>(out_logit);
}

// round 15
// speedup vs baseline: 1.0042x; 1.0042x over previous
#include <cuda_runtime.h>
#include <math.h>

#define H 1024
#define S 2048
#define VOCAB 50257

// ---------------- scratch (__device__ globals) -----------------------------
__device__ float g_h0[H];
__device__ float g_h1[H];
__device__ float g_energ[S];
__device__ float g_am[256];          // attention (max, expsum) partials
__device__ float g_as[256];
__device__ float g_ctx_part[256 * H];
__device__ float g_ctx[H];
__device__ float g_xout[2 * H];      // [h1, ctx]
__device__ float g_lm[64];           // logit lse partials
__device__ float g_ls[64];
__device__ unsigned g_ctr;           // completion counter for k_energy_ctx
__device__ unsigned g_done;          // release flag

__device__ __forceinline__ float wred(float v) {
#pragma unroll
    for (int o = 16; o; o >>= 1) v += __shfl_xor_sync(0xffffffffu, v, o);
    return v;
}
__device__ __forceinline__ float sig_(float x) { return 1.0f / (1.0f + expf(-x)); }

// online (max, expsum) merge — deterministic, guards empty partials
__device__ __forceinline__ void msmerge(float& m1, float& s1, float m2, float s2) {
    if (s2 == 0.0f) return;
    if (s1 == 0.0f) { m1 = m2; s1 = s2; return; }
    if (m2 > m1) { float tm = m1; m1 = m2; m2 = tm; float ts = s1; s1 = s2; s2 = ts; }
    s1 += s2 * expf(m2 - m1);
}

// ---------------- fused GRU layer: one BLOCK (256 thr) per output j --------
template <int N, bool GATHER>
__global__ void k_gru(const float* __restrict__ Wih, const float* __restrict__ Whh,
                      const float* __restrict__ bih, const float* __restrict__ bhh,
                      const float* __restrict__ xin,
                      const float* __restrict__ emb, const int* __restrict__ word,
                      const float* __restrict__ lastctx,
                      const float* __restrict__ hprev,
                      float* __restrict__ hout, float* __restrict__ hcopy,
                      float* __restrict__ xcopy) {
    __shared__ float smem[6][8];
    int j = blockIdx.x;
    int tid = threadIdx.x;
    int lane = tid & 31, warp = tid >> 5;

    // reset the energy_ctx completion counters once per run (runs before it)
    if (GATHER && j == 0 && tid == 0) { g_ctr = 0; g_done = 0; }

    const float4* wr4 = reinterpret_cast<const float4*>(Wih + (size_t)j * N);
    const float4* wz4 = reinterpret_cast<const float4*>(Wih + (size_t)(H + j) * N);
    const float4* wn4 = reinterpret_cast<const float4*>(Wih + (size_t)(2 * H + j) * N);
    const float4* ur4 = reinterpret_cast<const float4*>(Whh + (size_t)j * H);
    const float4* uz4 = reinterpret_cast<const float4*>(Whh + (size_t)(H + j) * H);
    const float4* un4 = reinterpret_cast<const float4*>(Whh + (size_t)(2 * H + j) * H);
    const float4* h4  = reinterpret_cast<const float4*>(hprev);

    float ir = 0.f, iz = 0.f, in_ = 0.f, hr = 0.f, hz = 0.f, hn = 0.f;

    if (GATHER) {
        const float4* e4 = reinterpret_cast<const float4*>(emb) + (size_t)word[0] * (H / 4);
        const float4* c4 = reinterpret_cast<const float4*>(lastctx);
#pragma unroll
        for (int i = tid; i < N / 4; i += 256) {
            float4 xv = (i < H / 4) ? e4[i] : c4[i - H / 4];
            float4 a = wr4[i], b = wz4[i], c = wn4[i];
            ir  += a.x * xv.x + a.y * xv.y + a.z * xv.z + a.w * xv.w;
            iz  += b.x * xv.x + b.y * xv.y + b.z * xv.z + b.w * xv.w;
            in_ += c.x * xv.x + c.y * xv.y + c.z * xv.z + c.w * xv.w;
        }
    } else {
        const float4* x4 = reinterpret_cast<const float4*>(xin);
#pragma unroll
        for (int i = tid; i < N / 4; i += 256) {
            float4 xv = x4[i];
            float4 a = wr4[i], b = wz4[i], c = wn4[i];
            ir  += a.x * xv.x + a.y * xv.y + a.z * xv.z + a.w * xv.w;
            iz  += b.x * xv.x + b.y * xv.y + b.z * xv.z + b.w * xv.w;
            in_ += c.x * xv.x + c.y * xv.y + c.z * xv.z + c.w * xv.w;
        }
    }
    {   // H/4 = 256 float4 -> exactly one iteration per thread
        float4 hv = h4[tid];
        float4 a = ur4[tid], b = uz4[tid], c = un4[tid];
        hr = a.x * hv.x + a.y * hv.y + a.z * hv.z + a.w * hv.w;
        hz = b.x * hv.x + b.y * hv.y + b.z * hv.z + b.w * hv.w;
        hn = c.x * hv.x + c.y * hv.y + c.z * hv.z + c.w * hv.w;
    }
    ir = wred(ir); iz = wred(iz); in_ = wred(in_);
    hr = wred(hr); hz = wred(hz); hn = wred(hn);
    if (lane == 0) {
        smem[0][warp] = ir; smem[1][warp] = iz; smem[2][warp] = in_;
        smem[3][warp] = hr; smem[4][warp] = hz; smem[5][warp] = hn;
    }
    __syncthreads();
    if (tid == 0) {
        float v[6];
#pragma unroll
        for (int g = 0; g < 6; ++g) {
            float s = smem[g][0];
#pragma unroll
            for (int w = 1; w < 8; ++w) s += smem[g][w];
            v[g] = s;
        }
        float r  = sig_((v[0] + bih[j]) + (v[3] + bhh[j]));
        float z  = sig_((v[1] + bih[H + j]) + (v[4] + bhh[H + j]));
        float nn = tanhf((v[2] + bih[2 * H + j]) + r * (v[5] + bhh[2 * H + j]));
        float h  = (1.0f - z) * nn + z * hprev[j];
        hout[j] = h;
        hcopy[j] = h;
        if (xcopy) xcopy[j] = h;
    }
}

// ---------------- energies + partial context + fused final reduce ----------
// 256 blocks x 256 threads; warp per s-row (8 rows/block).
// Phase 1 (all blocks): energies, block-local softmax partial, unnormalized
//   partial context written to g_ctx_part.
// Phase 2 (last 32 blocks to finish, after release flag): each handles 1/32
//   of the d-space: global (M,Z) tree, attention weights, final ctx.
__global__ void k_energy_ctx(const float* __restrict__ enc, const float* __restrict__ h1,
                             float* __restrict__ ctx_out, float* __restrict__ attn_out) {
    __shared__ float se[8];
    __shared__ float sbuf[1024];            // phase1: sctx; phase2: sm/ss/ssc/spart
    __shared__ unsigned srank;
    int tid = threadIdx.x;
    int lane = tid & 31, warp = tid >> 5;
    int s = blockIdx.x * 8 + warp;

    const float4* w4 = reinterpret_cast<const float4*>(enc) + (size_t)s * 256;
    const float4* x4 = reinterpret_cast<const float4*>(h1);

    float4 row[8];                          // this lane's slice of the enc row
    float e = 0.f;
#pragma unroll
    for (int k = 0; k < 8; ++k) {
        float4 a = w4[lane + 32 * k];
        float4 c = x4[lane + 32 * k];
        row[k] = a;
        e += a.x * c.x + a.y * c.y + a.z * c.z + a.w * c.w;
    }
    e = wred(e);
    e = __shfl_sync(0xffffffffu, e, 0);
    if (lane == 0) { g_energ[s] = e; se[warp] = e; }

    float4* sctx4 = reinterpret_cast<float4*>(sbuf);
    sctx4[tid] = make_float4(0.f, 0.f, 0.f, 0.f);
    __syncthreads();

    float m = se[0];
#pragma unroll
    for (int w = 1; w < 8; ++w) m = fmaxf(m, se[w]);
    float wgt = expf(e - m);

    // deterministic warp-ordered accumulation into smem
#pragma unroll
    for (int w = 0; w < 8; ++w) {
        if (warp == w) {
#pragma unroll
            for (int k = 0; k < 8; ++k) {
                int i = lane + 32 * k;
                float4 acc = sctx4[i];
                acc.x += wgt * row[k].x; acc.y += wgt * row[k].y;
                acc.z += wgt * row[k].z; acc.w += wgt * row[k].w;
                sctx4[i] = acc;
            }
        }
        __syncthreads();
    }

    reinterpret_cast<float4*>(g_ctx_part + (size_t)blockIdx.x * H)[tid] = sctx4[tid];
    if (tid == 0) {
        float sum = 0.f;
#pragma unroll
        for (int w = 0; w < 8; ++w) sum += expf(se[w] - m);
        g_am[blockIdx.x] = m;
        g_as[blockIdx.x] = sum;
    }

    // ---- completion protocol ----
    __threadfence();                        // partials visible before count
    __syncthreads();                        // all threads' writes fenced
    if (tid == 0) srank = atomicAdd(&g_ctr, 1);
    __syncthreads();
    unsigned rank = srank;
    if (rank == 255) {                      // all 256 partials are visible
        __threadfence();
        if (tid == 0) atomicExch(&g_done, 1);
    }
    if (rank < 224) return;                 // not one of the last 32

    // ---- phase 2: last 32 blocks each reduce one 32-d slice ----
    if (tid == 0) {
        while (atomicAdd(&g_done, 0) == 0) __nanosleep(64);
    }
    __syncthreads();
    __threadfence();
    int slice = (int)rank - 224;            // 0..31
    int dbase = slice * 32;

    float* sm  = sbuf;                      // reuse: [0,256)
    float* ss  = sbuf + 256;                // [256,512)
    float* ssc = sbuf + 512;                // [512,768)
    float* spart = sbuf + 768;              // [768,1024) -> [8][32]
    __syncthreads();                        // done with sctx4 contents
    sm[tid] = g_am[tid]; ss[tid] = g_as[tid];
    __syncthreads();
    float myM = sm[tid];
#pragma unroll
    for (int off = 128; off >= 1; off >>= 1) {
        if (tid < off) msmerge(sm[tid], ss[tid], sm[tid + off], ss[tid + off]);
        __syncthreads();
    }
    float M = sm[0], Z = ss[0];
    __syncthreads();
    ssc[tid] = expf(myM - M);
    __syncthreads();
    float invZ = 1.0f / Z;

    if (tid < 64) {
        int sidx = slice * 64 + tid;
        attn_out[sidx] = expf(g_energ[sidx] - M) * invZ;
    }

    // warp w sums b in [32w, 32w+32) for d = dbase + lane (coalesced)
    float acc = 0.f;
#pragma unroll
    for (int i = 0; i < 32; ++i) {
        int b = warp * 32 + i;
        acc += ssc[b] * g_ctx_part[(size_t)b * H + dbase + lane];
    }
    spart[warp * 32 + lane] = acc;
    __syncthreads();
    if (warp == 0) {
        float sum = spart[lane];
#pragma unroll
        for (int w = 1; w < 8; ++w) sum += spart[w * 32 + lane];
        float c = sum * invZ;
        int d = dbase + lane;
        g_ctx[d] = c;
        ctx_out[d] = c;
        g_xout[H + d] = c;
    }
}

// vocab GEMV: warp per row, full 2048 cols, bias fused (R5 plain version)
__global__ void k_vocab(const float* __restrict__ W, const float* __restrict__ b,
                        float* __restrict__ logits) {
    int v = (blockIdx.x * blockDim.x + threadIdx.x) >> 5;
    int lane = threadIdx.x & 31;
    if (v >= VOCAB) return;
    const float4* w4 = reinterpret_cast<const float4*>(W) + (size_t)v * 512;
    const float4* x4 = reinterpret_cast<const float4*>(g_xout);
    float s = 0.f;
#pragma unroll 8
    for (int i = lane; i < 512; i += 32) {
        float4 a = w4[i], c = x4[i];
        s += a.x * c.x + a.y * c.y + a.z * c.z + a.w * c.w;
    }
    s = wred(s);
    if (lane == 0) logits[v] = s + b[v];
}

// logit lse stage 1: 64 blocks x 256 threads, online (m,s) per block
__global__ void k_lse1(const float* __restrict__ logits) {
    __shared__ float sm[8], ss[8];
    const int CH = 786;
    int b = blockIdx.x;
    int lo = b * CH;
    int hi = min(lo + CH, VOCAB);
    int lane = threadIdx.x & 31, warp = threadIdx.x >> 5;
    float m = -INFINITY, s = 0.f;
    for (int v = lo + threadIdx.x; v < hi; v += 256) {
        float x = logits[v];
        if (x > m) { s = s * expf(m - x) + 1.0f; m = x; }
        else s += expf(x - m);
    }
#pragma unroll
    for (int o = 16; o; o >>= 1) {
        float m2 = __shfl_xor_sync(0xffffffffu, m, o);
        float s2 = __shfl_xor_sync(0xffffffffu, s, o);
        msmerge(m, s, m2, s2);
    }
    if (lane == 0) { sm[warp] = m; ss[warp] = s; }
    __syncthreads();
    if (threadIdx.x == 0) {
        float M = sm[0], Ssum = ss[0];
#pragma unroll
        for (int w = 1; w < 8; ++w) msmerge(M, Ssum, sm[w], ss[w]);
        g_lm[b] = M; g_ls[b] = Ssum;
    }
}

// finalize: each block recomputes the final LSE from 64 partials (L2-hot),
// then subtracts. Deterministic identical tree in every block.
__global__ void k_finalize(float* __restrict__ logits) {
    __shared__ float sm[64], ss[64];
    int t = threadIdx.x;
    if (t < 64) { sm[t] = g_lm[t]; ss[t] = g_ls[t]; }
    __syncthreads();
#pragma unroll
    for (int off = 32; off >= 1; off >>= 1) {
        if (t < off) msmerge(sm[t], ss[t], sm[t + off], ss[t + off]);
        __syncthreads();
    }
    float lse = sm[0] + logf(ss[0]);
    int v = blockIdx.x * blockDim.x + t;
    if (v < VOCAB) logits[v] -= lse;
}

// ---------------- launch ---------------------------------------------------

extern "C" void kernel_launch(void* const* d_in, const int* in_sizes, int n_in,
                              void* d_out, int out_size) {
    const int*   word     = (const int*)  d_in[0];
    const float* last_ctx = (const float*)d_in[1];
    const float* last_hid = (const float*)d_in[2];   // (2,1,H)
    const float* enc      = (const float*)d_in[3];   // (S,1,H)
    const float* emb      = (const float*)d_in[4];
    const float* W_ih0    = (const float*)d_in[5];
    const float* W_hh0    = (const float*)d_in[6];
    const float* b_ih0    = (const float*)d_in[7];
    const float* b_hh0    = (const float*)d_in[8];
    const float* W_ih1    = (const float*)d_in[9];
    const float* W_hh1    = (const float*)d_in[10];
    const float* b_ih1    = (const float*)d_in[11];
    const float* b_hh1    = (const float*)d_in[12];
    const float* W_out    = (const float*)d_in[13];
    const float* b_out    = (const float*)d_in[14];

    float* out       = (float*)d_out;
    float* out_logit = out;                  // [0, V)
    float* out_ctx   = out + VOCAB;          // context
    float* out_h0    = out + VOCAB + H;      // hidden[0]
    float* out_h1    = out + VOCAB + 2 * H;  // hidden[1]
    float* out_attn  = out + VOCAB + 3 * H;  // attn weights

    float *ph0, *ph1, *pxout;
    cudaGetSymbolAddress((void**)&ph0, g_h0);
    cudaGetSymbolAddress((void**)&ph1, g_h1);
    cudaGetSymbolAddress((void**)&pxout, g_xout);

    // 1-2) fused GRU layers; layer 1 also writes g_xout[0..H) = h1
    k_gru<2048, true><<<H, 256>>>(W_ih0, W_hh0, b_ih0, b_hh0, nullptr,
                                  emb, word, last_ctx, last_hid, ph0, out_h0,
                                  (float*)nullptr);
    k_gru<1024, false><<<H, 256>>>(W_ih1, W_hh1, b_ih1, b_hh1, ph0,
                                   nullptr, nullptr, nullptr, last_hid + H, ph1, out_h1,
                                   pxout);

    // 3) attention: single kernel (energies + partials + fused final reduce)
    k_energy_ctx<<<256, 256>>>(enc, ph1, out_ctx, out_attn);

    // 4) vocab logits (bias fused)
    k_vocab<<<(VOCAB * 32 + 255) / 256, 256>>>(W_out, b_out, out_logit);

    // 5-6) log_softmax
    k_lse1<<<64, 256>>>(out_logit);
    k_finalize<<<(VOCAB + 255) / 256, 256>>>(out_logit);
}